// round 1
// baseline (speedup 1.0000x reference)
#include <cuda_runtime.h>
#include <cuda_bf16.h>

#define LATDIM 128
#define HEADS 4
#define MAXN 100000
#define MAXE 600000

// Scratch (allocation-free: device globals)
__device__ float g_Q[(size_t)MAXN * LATDIM];
__device__ float g_K[(size_t)MAXN * LATDIM];
__device__ float g_V[(size_t)MAXN * LATDIM];
__device__ float g_expAtt[(size_t)MAXE * HEADS];
__device__ float g_attNorm[(size_t)MAXN * HEADS];

// ---------------- packed fp32x2 helpers (Blackwell) ----------------
__device__ __forceinline__ unsigned long long pack2(float x, float y) {
    unsigned long long r;
    asm("mov.b64 %0, {%1, %2};" : "=l"(r) : "f"(x), "f"(y));
    return r;
}
__device__ __forceinline__ void fma2(unsigned long long& d,
                                     unsigned long long a,
                                     unsigned long long b) {
    asm("fma.rn.f32x2 %0, %1, %2, %0;" : "+l"(d) : "l"(a), "l"(b));
}

// ---------------- zero out + attNorm ----------------
__global__ void zero_kernel(float* __restrict__ out, int n_out, int n_norm) {
    int stride = gridDim.x * blockDim.x;
    int i0 = blockIdx.x * blockDim.x + threadIdx.x;
    for (int i = i0; i < n_out; i += stride) out[i] = 0.0f;
    for (int i = i0; i < n_norm; i += stride) g_attNorm[i] = 0.0f;
}

// ---------------- QKV GEMM: [N,128] x [128,128] x3, fp32 via f32x2 ----------------
// Block: 256 threads, M-tile = 128 rows. Each thread: 8 rows x 8 cols.
// Dynamic smem: As (128 x 128, padded stride 132) + Ws (128 x 128).
#define AS_STRIDE 132
__global__ void __launch_bounds__(256, 1)
qkv_gemm(const float* __restrict__ embeds,
         const float* __restrict__ qT,
         const float* __restrict__ kT,
         const float* __restrict__ vT,
         int N) {
    extern __shared__ float smem[];
    float* As = smem;                       // 128 * 132 floats
    float* Ws = smem + 128 * AS_STRIDE;     // 128 * 128 floats

    const int tid = threadIdx.x;
    const int m0 = blockIdx.x * 128;

    // Load A tile (128 rows x 128 cols), zero-fill past N.
    for (int i = tid; i < 128 * 32; i += 256) {
        int m = i >> 5;
        int k4 = i & 31;
        float4 v = make_float4(0.f, 0.f, 0.f, 0.f);
        int gm = m0 + m;
        if (gm < N) v = ((const float4*)embeds)[(size_t)gm * 32 + k4];
        *(float4*)&As[m * AS_STRIDE + k4 * 4] = v;
    }

    const float* Wsrc[3] = {qT, kT, vT};

    const int ty = tid >> 4;       // 0..15
    const int tx = tid & 15;       // 0..15
    const int mrow = ty * 8;
    const int ncol = tx * 8;

    for (int w = 0; w < 3; ++w) {
        __syncthreads();  // previous compute done (and As loads on w==0)
        const float* W = Wsrc[w];
        for (int i = tid; i < 128 * 32; i += 256) {
            ((float4*)Ws)[i] = ((const float4*)W)[i];
        }
        __syncthreads();

        unsigned long long acc[8][4];
#pragma unroll
        for (int i = 0; i < 8; ++i)
#pragma unroll
            for (int j = 0; j < 4; ++j) acc[i][j] = 0ull;

#pragma unroll 4
        for (int k = 0; k < 128; ++k) {
            float a[8];
#pragma unroll
            for (int i = 0; i < 8; ++i) a[i] = As[(mrow + i) * AS_STRIDE + k];
            float4 b0 = *(const float4*)&Ws[k * 128 + ncol];
            float4 b1 = *(const float4*)&Ws[k * 128 + ncol + 4];
            unsigned long long bp[4];
            bp[0] = pack2(b0.x, b0.y);
            bp[1] = pack2(b0.z, b0.w);
            bp[2] = pack2(b1.x, b1.y);
            bp[3] = pack2(b1.z, b1.w);
#pragma unroll
            for (int i = 0; i < 8; ++i) {
                unsigned long long ap = pack2(a[i], a[i]);
#pragma unroll
                for (int j = 0; j < 4; ++j) fma2(acc[i][j], ap, bp[j]);
            }
        }

        // Store 8x8 tile
        float* D = (w == 0) ? g_Q : (w == 1) ? g_K : g_V;
#pragma unroll
        for (int i = 0; i < 8; ++i) {
            int gm = m0 + mrow + i;
            if (gm < N) {
                float o[8];
#pragma unroll
                for (int j = 0; j < 4; ++j) {
                    float2 f = *(float2*)&acc[i][j];
                    o[2 * j] = f.x;
                    o[2 * j + 1] = f.y;
                }
                *(float4*)&D[(size_t)gm * 128 + ncol] = *(float4*)&o[0];
                *(float4*)&D[(size_t)gm * 128 + ncol + 4] = *(float4*)&o[4];
            }
        }
    }
}

// ---------------- Edge pass A: per-edge per-head logits + exp + segment-sum ----------------
// One warp per edge. lane holds dims [4*lane, 4*lane+4) -> head = lane>>3.
__global__ void __launch_bounds__(256)
edge_att(const int* __restrict__ rows, const int* __restrict__ cols,
         const float* __restrict__ filt, int E) {
    int e = (blockIdx.x * blockDim.x + threadIdx.x) >> 5;
    int lane = threadIdx.x & 31;
    if (e >= E) return;
    int r = __ldg(&rows[e]);
    int c = __ldg(&cols[e]);

    float4 q = ((const float4*)g_Q)[(size_t)r * 32 + lane];
    float4 k = ((const float4*)g_K)[(size_t)c * 32 + lane];
    float p = q.x * k.x + q.y * k.y + q.z * k.z + q.w * k.w;
    // reduce within each 8-lane head group
    p += __shfl_xor_sync(0xffffffffu, p, 4);
    p += __shfl_xor_sync(0xffffffffu, p, 2);
    p += __shfl_xor_sync(0xffffffffu, p, 1);

    if ((lane & 7) == 0) {
        int h = lane >> 3;
        float att = fminf(fmaxf(p, -10.0f), 10.0f) + __ldg(&filt[(size_t)c * 4 + h]);
        float ea = expf(att);
        g_expAtt[(size_t)e * 4 + h] = ea;
        atomicAdd(&g_attNorm[(size_t)r * 4 + h], ea);
    }
}

// ---------------- Edge pass B: weighted V scatter-add ----------------
__global__ void __launch_bounds__(256)
edge_agg(const int* __restrict__ rows, const int* __restrict__ cols,
         float* __restrict__ out, int E) {
    int e = (blockIdx.x * blockDim.x + threadIdx.x) >> 5;
    int lane = threadIdx.x & 31;
    if (e >= E) return;
    int r = __ldg(&rows[e]);
    int c = __ldg(&cols[e]);
    int h = lane >> 3;

    float wgt = g_expAtt[(size_t)e * 4 + h] / (g_attNorm[(size_t)r * 4 + h] + 1e-8f);
    float4 v = ((const float4*)g_V)[(size_t)c * 32 + lane];
    v.x *= wgt; v.y *= wgt; v.z *= wgt; v.w *= wgt;

    float* dst = out + (size_t)r * 128 + lane * 4;
    asm volatile("red.global.add.v4.f32 [%0], {%1, %2, %3, %4};"
                 :: "l"(dst), "f"(v.x), "f"(v.y), "f"(v.z), "f"(v.w)
                 : "memory");
}

// ---------------- launch ----------------
extern "C" void kernel_launch(void* const* d_in, const int* in_sizes, int n_in,
                              void* d_out, int out_size) {
    const float* embeds = (const float*)d_in[0];
    const float* qT = (const float*)d_in[1];
    const float* kT = (const float*)d_in[2];
    const float* vT = (const float*)d_in[3];
    const float* filt = (const float*)d_in[4];
    const int* rows = (const int*)d_in[5];
    const int* cols = (const int*)d_in[6];
    float* out = (float*)d_out;

    int N = in_sizes[0] / LATDIM;
    int E = in_sizes[5];

    // GEMM needs 128*132*4 + 128*128*4 = 67584 + 65536 = 133120 B dynamic smem
    static const int GEMM_SMEM = 128 * AS_STRIDE * 4 + 128 * 128 * 4;
    cudaFuncSetAttribute(qkv_gemm, cudaFuncAttributeMaxDynamicSharedMemorySize, GEMM_SMEM);

    zero_kernel<<<512, 256>>>(out, N * LATDIM, N * HEADS);
    qkv_gemm<<<(N + 127) / 128, 256, GEMM_SMEM>>>(embeds, qT, kT, vT, N);

    int blocksE = (E * 32 + 255) / 256;
    edge_att<<<blocksE, 256>>>(rows, cols, filt, E);
    edge_agg<<<blocksE, 256>>>(rows, cols, out, E);
}